// round 14
// baseline (speedup 1.0000x reference)
#include <cuda_runtime.h>
#include <cuda_fp16.h>
#include <cstdint>
#include <math.h>

#define B_DIM 8192
#define DIN   10
#define H_DIM 1900
#define H4    7600
#define KP    1920          // padded K (both GEMMs)
#define NP_Z  7680          // padded N for gate GEMM (30 blocks of 256)
#define NP_M  2048          // padded N for m GEMM   (8 blocks of 256)
#define KT    32            // k-tile
#define NKT   60            // 1920/32

// ------------------------------------------------------------------
// static device scratch (zero-initialized at load; pads never written stay 0)
// ------------------------------------------------------------------
__device__ float g_sx [H4];
__device__ float g_sh [H4];
__device__ float g_smx[H_DIM];
__device__ float g_smh[H_DIM];
__device__ unsigned short g_xm16[(size_t)B_DIM * H_DIM]; // inputs @ wmx_n (fp16)
__device__ unsigned short g_zx16[(size_t)B_DIM * H4];    // inputs @ wx_n + b (fp16, n=j*4+g)
__device__ unsigned short g_m16 [(size_t)B_DIM * KP];    // m, fp16
__device__ unsigned short g_h16 [(size_t)B_DIM * KP];    // h_prev, fp16
__device__ unsigned short g_wh16[(size_t)NP_Z * KP];     // wh_n transposed+interleaved fp16
__device__ unsigned short g_wmh16[(size_t)NP_M * KP];    // wmh_n transposed fp16

// ------------------------------------------------------------------
__device__ __forceinline__ uint32_t smem_u32(const void* p) {
    uint32_t a;
    asm("{ .reg .u64 t; cvta.to.shared.u64 t, %1; cvt.u32.u64 %0, t; }" : "=r"(a) : "l"(p));
    return a;
}
__device__ __forceinline__ void ldsm_x4(uint32_t (&r)[4], uint32_t addr) {
    asm volatile("ldmatrix.sync.aligned.m8n8.x4.shared.b16 {%0,%1,%2,%3}, [%4];"
        : "=r"(r[0]), "=r"(r[1]), "=r"(r[2]), "=r"(r[3]) : "r"(addr));
}
__device__ __forceinline__ void mma16816(float (&d)[4], const uint32_t (&a)[4],
                                         uint32_t b0, uint32_t b1) {
    asm volatile("mma.sync.aligned.m16n8k16.row.col.f32.f16.f16.f32 "
        "{%0,%1,%2,%3}, {%4,%5,%6,%7}, {%8,%9}, {%0,%1,%2,%3};"
        : "+f"(d[0]), "+f"(d[1]), "+f"(d[2]), "+f"(d[3])
        : "r"(a[0]), "r"(a[1]), "r"(a[2]), "r"(a[3]), "r"(b0), "r"(b1));
}
__device__ __forceinline__ float sigmoidf_(float x) { return 1.0f / (1.0f + __expf(-x)); }
__device__ __forceinline__ unsigned short f2h_bits(float v) {
    return __half_as_ushort(__float2half(v));
}

// ------------------------------------------------------------------
// per-column l2 scale, parallel over rows: block = 32 cols x 8 row-lanes
// ------------------------------------------------------------------
__global__ void colnorm_kernel(const float* __restrict__ w, const float* __restrict__ g,
                               float* __restrict__ s, int rows, int cols) {
    __shared__ float red[8][33];
    const int jl = threadIdx.x & 31, rl = threadIdx.x >> 5;
    const int j = blockIdx.x * 32 + jl;
    float acc = 0.f;
    if (j < cols) {
        for (int i = rl; i < rows; i += 8) {
            float a = w[(size_t)i * cols + j];
            acc += a * a;
        }
    }
    red[rl][jl] = acc;
    __syncthreads();
    if (rl == 0 && j < cols) {
        float t = 0.f;
#pragma unroll
        for (int r = 0; r < 8; ++r) t += red[r][jl];
        s[j] = g[j] * rsqrtf(fmaxf(t, 1e-12f));
    }
}

// ------------------------------------------------------------------
// K=10 input GEMMs (fp16 outputs)
// ------------------------------------------------------------------
__global__ void input_gemm_plain(const float* __restrict__ x, const float* __restrict__ w,
                                 const float* __restrict__ s, unsigned short* __restrict__ out) {
    long long idx = (long long)blockIdx.x * blockDim.x + threadIdx.x;
    if (idx >= (long long)B_DIM * H_DIM) return;
    int b = (int)(idx / H_DIM), j = (int)(idx - (long long)b * H_DIM);
    const float* xr = x + b * DIN;
    float acc = 0.f;
#pragma unroll
    for (int k = 0; k < DIN; ++k) acc += xr[k] * w[(size_t)k * H_DIM + j];
    out[idx] = f2h_bits(acc * s[j]);
}
// gate-interleaved zx: out[b][j*4+g] = (x @ wx_n)[b][g*1900+j] + bias
__global__ void input_gemm_gates(const float* __restrict__ x, const float* __restrict__ w,
                                 const float* __restrict__ s, const float* __restrict__ bias,
                                 unsigned short* __restrict__ out) {
    long long idx = (long long)blockIdx.x * blockDim.x + threadIdx.x;
    if (idx >= (long long)B_DIM * H4) return;
    int b = (int)(idx / H4), n = (int)(idx - (long long)b * H4);
    int j = n >> 2, g = n & 3;
    int col = g * H_DIM + j;
    const float* xr = x + b * DIN;
    float acc = 0.f;
#pragma unroll
    for (int k = 0; k < DIN; ++k) acc += xr[k] * w[(size_t)k * H4 + col];
    out[idx] = f2h_bits(acc * s[col] + bias[col]);
}

// ------------------------------------------------------------------
// fp32 -> fp16 with K-padding (row-major [rows, KP])
// ------------------------------------------------------------------
__global__ void pad_h16_kernel(const float* __restrict__ x, unsigned short* __restrict__ o,
                               int cols, long long total) {
    long long idx = (long long)blockIdx.x * blockDim.x + threadIdx.x;
    if (idx >= total) return;
    int c = (int)(idx % KP);
    long long r = idx / KP;
    float v = (c < cols) ? x[r * cols + c] : 0.f;
    o[idx] = f2h_bits(v);
}

// ------------------------------------------------------------------
// transpose + scale -> single fp16:  o[n(c)][k] = w[k][c] * s[c]
// ILV=1: n = (c%1900)*4 + c/1900 (gate interleave), else n = c
// ------------------------------------------------------------------
template<int ILV>
__global__ void transp_h16_kernel(const float* __restrict__ w, const float* __restrict__ s,
                                  unsigned short* __restrict__ o16, int K, int NC) {
    __shared__ float tile[32][33];
    int c0 = blockIdx.x * 32, k0 = blockIdx.y * 32;
    int tx = threadIdx.x, ty = threadIdx.y;
    int c = c0 + tx, k = k0 + ty;
    float v = 0.f;
    if (c < NC && k < K) v = w[(size_t)k * NC + c] * s[c];
    tile[ty][tx] = v;
    __syncthreads();
    c = c0 + ty; k = k0 + tx;
    if (c < NC) {
        float val = tile[tx][ty];
        int n = ILV ? ((c % H_DIM) * 4 + c / H_DIM) : c;
        o16[(size_t)n * KP + k] = f2h_bits(val);
    }
}

// ------------------------------------------------------------------
// mma.sync fp16 GEMM (1-term), 128x256x32 CTA tile, 512 threads,
// 16 warps (warp tile 32x64, 64 acc regs), 3-stage cp.async, 1 CTA/SM.
// MODE 0: D = h16 @ wmh16 ; m = D*xm16 -> fp16
// MODE 1: D = m16 @ wh16 ; fused gate epilogue -> (h,c)
// ------------------------------------------------------------------
#define TILE_A  8192               // 128 x 32 x 2B
#define TILE_Bb 16384              // 256 x 32 x 2B
#define STAGE_B (TILE_A + TILE_Bb) // 24 KB
#define SMEM_T  (3 * STAGE_B)      // 72 KB

template<int MODE>
__global__ __launch_bounds__(512, 1)
void tc_gemm_kernel(const unsigned short* __restrict__ A_,
                    const unsigned short* __restrict__ B_,
                    const unsigned short* __restrict__ xm16, const unsigned short* __restrict__ zx16,
                    const float* __restrict__ cprev,
                    float* __restrict__ outh, float* __restrict__ outc,
                    unsigned short* __restrict__ mout) {
    extern __shared__ char smem[];
    const uint32_t sb = smem_u32(smem);
    const int tid = threadIdx.x;
    const int wid = tid >> 5, lane = tid & 31;
    const int wm = wid & 3, wn = wid >> 2;          // warp tile: rows wm*32, cols wn*64
    const int lrow = lane & 15, lseg = lane >> 4;
    const int m0 = blockIdx.y * 128, n0 = blockIdx.x * 256;

    // row of KT=32 fp16 = 64 bytes = 4 x 16B units; swizzle u ^ (row&3)
    auto load_tile = [&](int st, int kt) {
        uint32_t base = sb + st * STAGE_B;
        {   // A tile: 512 slots of 16B, 1 per thread
            int row = tid >> 2, u = tid & 3;
            uint32_t so = base + row * 64 + ((u ^ (row & 3)) << 4);
            const void* gp = (const void*)(A_ + (size_t)(m0 + row) * KP + kt * KT + u * 8);
            asm volatile("cp.async.cg.shared.global [%0], [%1], 16;" :: "r"(so), "l"(gp));
        }
#pragma unroll
        for (int i = 0; i < 2; ++i) {  // B tile: 1024 slots
            int cid = tid + i * 512;
            int row = cid >> 2, u = cid & 3;
            uint32_t so = base + TILE_A + row * 64 + ((u ^ (row & 3)) << 4);
            const void* gp = (const void*)(B_ + (size_t)(n0 + row) * KP + kt * KT + u * 8);
            asm volatile("cp.async.cg.shared.global [%0], [%1], 16;" :: "r"(so), "l"(gp));
        }
        asm volatile("cp.async.commit_group;" ::: "memory");
    };

    float acc[2][8][4];
#pragma unroll
    for (int a = 0; a < 2; ++a)
#pragma unroll
        for (int b = 0; b < 8; ++b)
#pragma unroll
            for (int c = 0; c < 4; ++c) acc[a][b][c] = 0.f;

    load_tile(0, 0);
    load_tile(1, 1);

    int cur = 0;
    for (int kt = 0; kt < NKT; ++kt) {
        if (kt + 2 < NKT) {
            load_tile((cur + 2) % 3, kt + 2);
            asm volatile("cp.async.wait_group 2;" ::: "memory");
        } else if (kt + 1 < NKT) {
            asm volatile("cp.async.wait_group 1;" ::: "memory");
        } else {
            asm volatile("cp.async.wait_group 0;" ::: "memory");
        }
        __syncthreads();

        const uint32_t stb = sb + cur * STAGE_B;
#pragma unroll
        for (int ks = 0; ks < 2; ++ks) {
            uint32_t ah[2][4], bb[4][4];
#pragma unroll
            for (int mt = 0; mt < 2; ++mt) {
                int row = wm * 32 + mt * 16 + lrow;
                uint32_t sw = (uint32_t)(((ks * 2 + lseg) ^ (row & 3)) << 4) + (uint32_t)row * 64;
                ldsm_x4(ah[mt], stb + sw);
            }
#pragma unroll
            for (int q = 0; q < 4; ++q) {
                int row = wn * 64 + q * 16 + lrow;
                uint32_t sw = (uint32_t)(((ks * 2 + lseg) ^ (row & 3)) << 4) + (uint32_t)row * 64;
                ldsm_x4(bb[q], stb + TILE_A + sw);
            }
#pragma unroll
            for (int mt = 0; mt < 2; ++mt)
#pragma unroll
                for (int q = 0; q < 4; ++q) {
                    mma16816(acc[mt][2 * q + 0], ah[mt], bb[q][0], bb[q][2]);
                    mma16816(acc[mt][2 * q + 1], ah[mt], bb[q][1], bb[q][3]);
                }
        }
        __syncthreads();
        cur = (cur + 1) % 3;
    }

    // ---------------- epilogue ----------------
    // fragment: c0,c1 at (row = l/4, n = 2*(l%4)+{0,1}); c2,c3 at row+8
    const int qrow = lane >> 2, qcol = lane & 3;
#pragma unroll
    for (int mt = 0; mt < 2; ++mt) {
        const int r0 = m0 + wm * 32 + mt * 16 + qrow;   // and r0+8
#pragma unroll
        for (int nt = 0; nt < 8; ++nt) {
            const int nb = n0 + wn * 64 + nt * 8;
            float c0 = acc[mt][nt][0], c1 = acc[mt][nt][1];
            float c2 = acc[mt][nt][2], c3 = acc[mt][nt][3];
            if (MODE == 0) {
                const int n = nb + 2 * qcol;
                if (n < KP) {   // NP_M pad region beyond KP is not stored
#pragma unroll
                    for (int h = 0; h < 2; ++h) {
                        const int r = r0 + h * 8;
                        uint32_t hp = 0;
                        if (n + 1 < H_DIM) {
                            float2 xf = __half22float2(*(const __half2*)(xm16 + (size_t)r * H_DIM + n));
                            float v0 = (h ? c2 : c0), v1 = (h ? c3 : c1);
                            hp = ((uint32_t)f2h_bits(v1 * xf.y) << 16) | f2h_bits(v0 * xf.x);
                        }
                        *(uint32_t*)(mout + (size_t)r * KP + n) = hp;
                    }
                }
            } else {
                // exchange within lane pair: even lane holds (zi,zf), odd holds (zo,zu)
                float o0 = __shfl_xor_sync(0xffffffffu, c0, 1);
                float o1 = __shfl_xor_sync(0xffffffffu, c1, 1);
                float o2 = __shfl_xor_sync(0xffffffffu, c2, 1);
                float o3 = __shfl_xor_sync(0xffffffffu, c3, 1);
                if ((qcol & 1) == 0) {
                    const int j = (nb >> 2) + (qcol >> 1);
                    if (j < H_DIM) {
#pragma unroll
                        for (int h = 0; h < 2; ++h) {
                            const int r = r0 + h * 8;
                            const __half2* zp = (const __half2*)(zx16 + (size_t)r * H4 + 4 * j);
                            float2 f0 = __half22float2(zp[0]);
                            float2 f1 = __half22float2(zp[1]);
                            float zi = (h ? c2 : c0) + f0.x;
                            float zf = (h ? c3 : c1) + f0.y;
                            float zo = (h ? o2 : o0) + f1.x;
                            float zu = (h ? o3 : o1) + f1.y;
                            float iv = sigmoidf_(zi), fv = sigmoidf_(zf), ov = sigmoidf_(zo);
                            float uv = tanhf(zu);
                            size_t o = (size_t)r * H_DIM + j;
                            float c = fv * cprev[o] + iv * uv;
                            outh[o] = ov * tanhf(c);
                            outc[o] = c;
                        }
                    }
                }
            }
        }
    }
}

// ------------------------------------------------------------------
// launch — two-stream fork/join (graph-capture-safe event pattern)
// ------------------------------------------------------------------
extern "C" void kernel_launch(void* const* d_in, const int* in_sizes, int n_in,
                              void* d_out, int out_size) {
    const float* inputs = (const float*)d_in[0];
    const float* c_prev = (const float*)d_in[1];
    const float* h_prev = (const float*)d_in[2];
    const float* wx     = (const float*)d_in[3];
    const float* wh     = (const float*)d_in[4];
    const float* wmx    = (const float*)d_in[5];
    const float* wmh    = (const float*)d_in[6];
    const float* bvec   = (const float*)d_in[7];
    const float* gx     = (const float*)d_in[8];
    const float* gh     = (const float*)d_in[9];
    const float* gmx    = (const float*)d_in[10];
    const float* gmh    = (const float*)d_in[11];

    float* out_h = (float*)d_out;
    float* out_c = out_h + (size_t)B_DIM * H_DIM;

    float *sx, *sh, *smx, *smh;
    unsigned short *xm16, *zx16, *m16, *h16, *wh16, *wmh16;
    cudaGetSymbolAddress((void**)&sx,    g_sx);
    cudaGetSymbolAddress((void**)&sh,    g_sh);
    cudaGetSymbolAddress((void**)&smx,   g_smx);
    cudaGetSymbolAddress((void**)&smh,   g_smh);
    cudaGetSymbolAddress((void**)&xm16,  g_xm16);
    cudaGetSymbolAddress((void**)&zx16,  g_zx16);
    cudaGetSymbolAddress((void**)&m16,   g_m16);
    cudaGetSymbolAddress((void**)&h16,   g_h16);
    cudaGetSymbolAddress((void**)&wh16,  g_wh16);
    cudaGetSymbolAddress((void**)&wmh16, g_wmh16);

    cudaFuncSetAttribute(tc_gemm_kernel<0>, cudaFuncAttributeMaxDynamicSharedMemorySize, SMEM_T);
    cudaFuncSetAttribute(tc_gemm_kernel<1>, cudaFuncAttributeMaxDynamicSharedMemorySize, SMEM_T);

    // fork: side stream for the GEMM-z-only prep chain
    cudaStream_t s2;
    cudaEvent_t evF, evJ;
    cudaStreamCreateWithFlags(&s2, cudaStreamNonBlocking);
    cudaEventCreateWithFlags(&evF, cudaEventDisableTiming);
    cudaEventCreateWithFlags(&evJ, cudaEventDisableTiming);
    cudaEventRecord(evF, 0);
    cudaStreamWaitEvent(s2, evF, 0);

    // ---- chain B (s2): prep needed only by GEMM-z ----
    colnorm_kernel<<<(H4 + 31) / 32, 256, 0, s2>>>(wx, gx, sx, DIN, H4);
    colnorm_kernel<<<(H4 + 31) / 32, 256, 0, s2>>>(wh, gh, sh, H_DIM, H4);
    input_gemm_gates<<<(int)(((long long)B_DIM * H4 + 255) / 256), 256, 0, s2>>>(inputs, wx, sx, bvec, zx16);
    {
        dim3 blk(32, 32);
        dim3 gz((H4 + 31) / 32, KP / 32);
        transp_h16_kernel<1><<<gz, blk, 0, s2>>>(wh, sh, wh16, H_DIM, H4);
    }
    cudaEventRecord(evJ, s2);

    // ---- chain A (stream 0): GEMM-m path ----
    colnorm_kernel<<<(H_DIM + 31) / 32, 256>>>(wmx, gmx, smx, DIN, H_DIM);
    colnorm_kernel<<<(H_DIM + 31) / 32, 256>>>(wmh, gmh, smh, H_DIM, H_DIM);
    input_gemm_plain<<<(int)(((long long)B_DIM * H_DIM + 255) / 256), 256>>>(inputs, wmx, smx, xm16);
    pad_h16_kernel<<<(int)(((long long)B_DIM * KP + 255) / 256), 256>>>(h_prev, h16, H_DIM, (long long)B_DIM * KP);
    {
        dim3 blk(32, 32);
        dim3 gm((H_DIM + 31) / 32, KP / 32);
        transp_h16_kernel<0><<<gm, blk>>>(wmh, smh, wmh16, H_DIM, H_DIM);
    }
    {
        dim3 grid(NP_M / 256, B_DIM / 128);
        tc_gemm_kernel<0><<<grid, 512, SMEM_T>>>(h16, wmh16,
                                                 xm16, nullptr, nullptr, nullptr, nullptr, m16);
    }

    // join, then GEMM-z
    cudaStreamWaitEvent(0, evJ, 0);
    {
        dim3 grid(NP_Z / 256, B_DIM / 128);
        tc_gemm_kernel<1><<<grid, 512, SMEM_T>>>(m16, wh16,
                                                 nullptr, zx16, c_prev, out_h, out_c, nullptr);
    }
    (void)in_sizes; (void)n_in; (void)out_size;
}

// round 15
// speedup vs baseline: 1.4046x; 1.4046x over previous
#include <cuda_runtime.h>
#include <cuda_fp16.h>
#include <cstdint>
#include <math.h>

#define B_DIM 8192
#define DIN   10
#define H_DIM 1900
#define H4    7600
#define KP    1920          // padded K (both GEMMs)
#define NP_Z  7680          // padded N for gate GEMM (60 blocks of 128)
#define NP_M  1920          // padded N for m GEMM   (15 blocks of 128)
#define KT    64            // k-tile
#define NKT   30            // 1920/64

// ------------------------------------------------------------------
// static device scratch (zero-initialized at load; pads never written stay 0)
// ------------------------------------------------------------------
__device__ float g_sx [H4];
__device__ float g_sh [H4];
__device__ float g_smx[H_DIM];
__device__ float g_smh[H_DIM];
__device__ unsigned short g_xm16[(size_t)B_DIM * H_DIM]; // inputs @ wmx_n (fp16)
__device__ unsigned short g_zx16[(size_t)B_DIM * H4];    // inputs @ wx_n + b (fp16, n=j*4+g)
__device__ unsigned short g_m16 [(size_t)B_DIM * KP];    // m, fp16
__device__ unsigned short g_h16 [(size_t)B_DIM * KP];    // h_prev, fp16
__device__ unsigned short g_wh16[(size_t)NP_Z * KP];     // wh_n transposed+interleaved fp16
__device__ unsigned short g_wmh16[(size_t)NP_M * KP];    // wmh_n transposed fp16

// ------------------------------------------------------------------
__device__ __forceinline__ uint32_t smem_u32(const void* p) {
    uint32_t a;
    asm("{ .reg .u64 t; cvta.to.shared.u64 t, %1; cvt.u32.u64 %0, t; }" : "=r"(a) : "l"(p));
    return a;
}
__device__ __forceinline__ void ldsm_x4(uint32_t (&r)[4], uint32_t addr) {
    asm volatile("ldmatrix.sync.aligned.m8n8.x4.shared.b16 {%0,%1,%2,%3}, [%4];"
        : "=r"(r[0]), "=r"(r[1]), "=r"(r[2]), "=r"(r[3]) : "r"(addr));
}
__device__ __forceinline__ void mma16816(float (&d)[4], const uint32_t (&a)[4],
                                         uint32_t b0, uint32_t b1) {
    asm volatile("mma.sync.aligned.m16n8k16.row.col.f32.f16.f16.f32 "
        "{%0,%1,%2,%3}, {%4,%5,%6,%7}, {%8,%9}, {%0,%1,%2,%3};"
        : "+f"(d[0]), "+f"(d[1]), "+f"(d[2]), "+f"(d[3])
        : "r"(a[0]), "r"(a[1]), "r"(a[2]), "r"(a[3]), "r"(b0), "r"(b1));
}
__device__ __forceinline__ float sigmoidf_(float x) { return 1.0f / (1.0f + __expf(-x)); }
__device__ __forceinline__ unsigned short f2h_bits(float v) {
    return __half_as_ushort(__float2half(v));
}

// ------------------------------------------------------------------
// per-column l2 scale, parallel over rows: block = 32 cols x 8 row-lanes
// ------------------------------------------------------------------
__global__ void colnorm_kernel(const float* __restrict__ w, const float* __restrict__ g,
                               float* __restrict__ s, int rows, int cols) {
    __shared__ float red[8][33];
    const int jl = threadIdx.x & 31, rl = threadIdx.x >> 5;
    const int j = blockIdx.x * 32 + jl;
    float acc = 0.f;
    if (j < cols) {
        for (int i = rl; i < rows; i += 8) {
            float a = w[(size_t)i * cols + j];
            acc += a * a;
        }
    }
    red[rl][jl] = acc;
    __syncthreads();
    if (rl == 0 && j < cols) {
        float t = 0.f;
#pragma unroll
        for (int r = 0; r < 8; ++r) t += red[r][jl];
        s[j] = g[j] * rsqrtf(fmaxf(t, 1e-12f));
    }
}

// ------------------------------------------------------------------
// K=10 input GEMMs (fp16 outputs)
// ------------------------------------------------------------------
__global__ void input_gemm_plain(const float* __restrict__ x, const float* __restrict__ w,
                                 const float* __restrict__ s, unsigned short* __restrict__ out) {
    long long idx = (long long)blockIdx.x * blockDim.x + threadIdx.x;
    if (idx >= (long long)B_DIM * H_DIM) return;
    int b = (int)(idx / H_DIM), j = (int)(idx - (long long)b * H_DIM);
    const float* xr = x + b * DIN;
    float acc = 0.f;
#pragma unroll
    for (int k = 0; k < DIN; ++k) acc += xr[k] * w[(size_t)k * H_DIM + j];
    out[idx] = f2h_bits(acc * s[j]);
}
// gate-interleaved zx: out[b][j*4+g] = (x @ wx_n)[b][g*1900+j] + bias
__global__ void input_gemm_gates(const float* __restrict__ x, const float* __restrict__ w,
                                 const float* __restrict__ s, const float* __restrict__ bias,
                                 unsigned short* __restrict__ out) {
    long long idx = (long long)blockIdx.x * blockDim.x + threadIdx.x;
    if (idx >= (long long)B_DIM * H4) return;
    int b = (int)(idx / H4), n = (int)(idx - (long long)b * H4);
    int j = n >> 2, g = n & 3;
    int col = g * H_DIM + j;
    const float* xr = x + b * DIN;
    float acc = 0.f;
#pragma unroll
    for (int k = 0; k < DIN; ++k) acc += xr[k] * w[(size_t)k * H4 + col];
    out[idx] = f2h_bits(acc * s[col] + bias[col]);
}

// ------------------------------------------------------------------
// fp32 -> fp16 with K-padding (row-major [rows, KP])
// ------------------------------------------------------------------
__global__ void pad_h16_kernel(const float* __restrict__ x, unsigned short* __restrict__ o,
                               int cols, long long total) {
    long long idx = (long long)blockIdx.x * blockDim.x + threadIdx.x;
    if (idx >= total) return;
    int c = (int)(idx % KP);
    long long r = idx / KP;
    float v = (c < cols) ? x[r * cols + c] : 0.f;
    o[idx] = f2h_bits(v);
}

// ------------------------------------------------------------------
// transpose + scale -> single fp16:  o[n(c)][k] = w[k][c] * s[c]
// ILV=1: n = (c%1900)*4 + c/1900 (gate interleave), else n = c
// ------------------------------------------------------------------
template<int ILV>
__global__ void transp_h16_kernel(const float* __restrict__ w, const float* __restrict__ s,
                                  unsigned short* __restrict__ o16, int K, int NC) {
    __shared__ float tile[32][33];
    int c0 = blockIdx.x * 32, k0 = blockIdx.y * 32;
    int tx = threadIdx.x, ty = threadIdx.y;
    int c = c0 + tx, k = k0 + ty;
    float v = 0.f;
    if (c < NC && k < K) v = w[(size_t)k * NC + c] * s[c];
    tile[ty][tx] = v;
    __syncthreads();
    c = c0 + ty; k = k0 + tx;
    if (c < NC) {
        float val = tile[tx][ty];
        int n = ILV ? ((c % H_DIM) * 4 + c / H_DIM) : c;
        o16[(size_t)n * KP + k] = f2h_bits(val);
    }
}

// ------------------------------------------------------------------
// mma.sync fp16 GEMM (1-term), 128x128x64 CTA tile, 8 warps (32x64 each),
// 2 stages x 32KB smem -> 2 CTAs/SM; halved sync rounds vs KT=32.
// MODE 0: D = h16 @ wmh16 ; m = D*xm16 -> fp16
// MODE 1: D = m16 @ wh16 ; fused gate epilogue -> (h,c)
// ------------------------------------------------------------------
#define TILE_B  16384              // one operand tile: 128 x 64 x 2B
#define STAGE_B (2 * TILE_B)       // 32 KB
#define SMEM_T  (2 * STAGE_B)      // 64 KB

template<int MODE>
__global__ __launch_bounds__(256, 2)
void tc_gemm_kernel(const unsigned short* __restrict__ A_,
                    const unsigned short* __restrict__ B_,
                    const unsigned short* __restrict__ xm16, const unsigned short* __restrict__ zx16,
                    const float* __restrict__ cprev,
                    float* __restrict__ outh, float* __restrict__ outc,
                    unsigned short* __restrict__ mout) {
    extern __shared__ char smem[];
    const uint32_t sb = smem_u32(smem);
    const int tid = threadIdx.x;
    const int wid = tid >> 5, lane = tid & 31;
    const int wm = wid & 3, wn = wid >> 2;          // warp tile: rows wm*32, cols wn*64
    const int lrow = lane & 15, lseg = lane >> 4;
    const int m0 = blockIdx.y * 128, n0 = blockIdx.x * 128;

    // row of KT=64 fp16 = 128 bytes = 8 x 16B units; swizzle u ^ (row&7)
    auto load_tile = [&](int st, int kt) {
        uint32_t base = sb + st * STAGE_B;
#pragma unroll
        for (int T = 0; T < 2; ++T) {
            const int rb = (T == 0) ? m0 : n0;
            const unsigned short* src = (T == 0) ? A_ : B_;
#pragma unroll
            for (int i = 0; i < 4; ++i) {
                int cid = tid + i * 256;
                int row = cid >> 3, u = cid & 7;
                uint32_t so = base + T * TILE_B + row * 128 + ((u ^ (row & 7)) << 4);
                const void* gp = (const void*)(src + (size_t)(rb + row) * KP + kt * KT + u * 8);
                asm volatile("cp.async.cg.shared.global [%0], [%1], 16;" :: "r"(so), "l"(gp));
            }
        }
        asm volatile("cp.async.commit_group;" ::: "memory");
    };

    float acc[2][8][4];
#pragma unroll
    for (int a = 0; a < 2; ++a)
#pragma unroll
        for (int b = 0; b < 8; ++b)
#pragma unroll
            for (int c = 0; c < 4; ++c) acc[a][b][c] = 0.f;

    load_tile(0, 0);

    for (int kt = 0; kt < NKT; ++kt) {
        const int cur = kt & 1;
        if (kt + 1 < NKT) {
            load_tile(cur ^ 1, kt + 1);
            asm volatile("cp.async.wait_group 1;" ::: "memory");
        } else {
            asm volatile("cp.async.wait_group 0;" ::: "memory");
        }
        __syncthreads();

        const uint32_t stb = sb + cur * STAGE_B;
#pragma unroll
        for (int ks = 0; ks < 4; ++ks) {
            uint32_t ah[2][4], bb[4][4];
#pragma unroll
            for (int mt = 0; mt < 2; ++mt) {
                int row = wm * 32 + mt * 16 + lrow;
                uint32_t sw = (uint32_t)(((ks * 2 + lseg) ^ (row & 7)) << 4) + (uint32_t)row * 128;
                ldsm_x4(ah[mt], stb + sw);
            }
#pragma unroll
            for (int q = 0; q < 4; ++q) {
                int row = wn * 64 + q * 16 + lrow;
                uint32_t sw = (uint32_t)(((ks * 2 + lseg) ^ (row & 7)) << 4) + (uint32_t)row * 128;
                ldsm_x4(bb[q], stb + TILE_B + sw);
            }
#pragma unroll
            for (int mt = 0; mt < 2; ++mt)
#pragma unroll
                for (int q = 0; q < 4; ++q) {
                    mma16816(acc[mt][2 * q + 0], ah[mt], bb[q][0], bb[q][2]);
                    mma16816(acc[mt][2 * q + 1], ah[mt], bb[q][1], bb[q][3]);
                }
        }
        __syncthreads();
    }

    // ---------------- epilogue ----------------
    // fragment: c0,c1 at (row = l/4, n = 2*(l%4)+{0,1}); c2,c3 at row+8
    const int qrow = lane >> 2, qcol = lane & 3;
#pragma unroll
    for (int mt = 0; mt < 2; ++mt) {
        const int r0 = m0 + wm * 32 + mt * 16 + qrow;   // and r0+8
#pragma unroll
        for (int nt = 0; nt < 8; ++nt) {
            const int nb = n0 + wn * 64 + nt * 8;
            float c0 = acc[mt][nt][0], c1 = acc[mt][nt][1];
            float c2 = acc[mt][nt][2], c3 = acc[mt][nt][3];
            if (MODE == 0) {
                const int n = nb + 2 * qcol;
                // H_DIM even -> a half2 pair is entirely valid or entirely pad
#pragma unroll
                for (int h = 0; h < 2; ++h) {
                    const int r = r0 + h * 8;
                    uint32_t hp = 0;
                    if (n + 1 < H_DIM) {
                        float2 xf = __half22float2(*(const __half2*)(xm16 + (size_t)r * H_DIM + n));
                        float v0 = (h ? c2 : c0), v1 = (h ? c3 : c1);
                        hp = ((uint32_t)f2h_bits(v1 * xf.y) << 16) | f2h_bits(v0 * xf.x);
                    }
                    *(uint32_t*)(mout + (size_t)r * KP + n) = hp;
                }
            } else {
                // exchange within lane pair: even lane holds (zi,zf), odd holds (zo,zu)
                float o0 = __shfl_xor_sync(0xffffffffu, c0, 1);
                float o1 = __shfl_xor_sync(0xffffffffu, c1, 1);
                float o2 = __shfl_xor_sync(0xffffffffu, c2, 1);
                float o3 = __shfl_xor_sync(0xffffffffu, c3, 1);
                if ((qcol & 1) == 0) {
                    const int j = (nb >> 2) + (qcol >> 1);
                    if (j < H_DIM) {
#pragma unroll
                        for (int h = 0; h < 2; ++h) {
                            const int r = r0 + h * 8;
                            const __half2* zp = (const __half2*)(zx16 + (size_t)r * H4 + 4 * j);
                            float2 f0 = __half22float2(zp[0]);
                            float2 f1 = __half22float2(zp[1]);
                            float zi = (h ? c2 : c0) + f0.x;
                            float zf = (h ? c3 : c1) + f0.y;
                            float zo = (h ? o2 : o0) + f1.x;
                            float zu = (h ? o3 : o1) + f1.y;
                            float iv = sigmoidf_(zi), fv = sigmoidf_(zf), ov = sigmoidf_(zo);
                            float uv = tanhf(zu);
                            size_t o = (size_t)r * H_DIM + j;
                            float c = fv * cprev[o] + iv * uv;
                            outh[o] = ov * tanhf(c);
                            outc[o] = c;
                        }
                    }
                }
            }
        }
    }
}

// ------------------------------------------------------------------
// launch — two-stream fork/join (graph-capture-safe event pattern)
// ------------------------------------------------------------------
extern "C" void kernel_launch(void* const* d_in, const int* in_sizes, int n_in,
                              void* d_out, int out_size) {
    const float* inputs = (const float*)d_in[0];
    const float* c_prev = (const float*)d_in[1];
    const float* h_prev = (const float*)d_in[2];
    const float* wx     = (const float*)d_in[3];
    const float* wh     = (const float*)d_in[4];
    const float* wmx    = (const float*)d_in[5];
    const float* wmh    = (const float*)d_in[6];
    const float* bvec   = (const float*)d_in[7];
    const float* gx     = (const float*)d_in[8];
    const float* gh     = (const float*)d_in[9];
    const float* gmx    = (const float*)d_in[10];
    const float* gmh    = (const float*)d_in[11];

    float* out_h = (float*)d_out;
    float* out_c = out_h + (size_t)B_DIM * H_DIM;

    float *sx, *sh, *smx, *smh;
    unsigned short *xm16, *zx16, *m16, *h16, *wh16, *wmh16;
    cudaGetSymbolAddress((void**)&sx,    g_sx);
    cudaGetSymbolAddress((void**)&sh,    g_sh);
    cudaGetSymbolAddress((void**)&smx,   g_smx);
    cudaGetSymbolAddress((void**)&smh,   g_smh);
    cudaGetSymbolAddress((void**)&xm16,  g_xm16);
    cudaGetSymbolAddress((void**)&zx16,  g_zx16);
    cudaGetSymbolAddress((void**)&m16,   g_m16);
    cudaGetSymbolAddress((void**)&h16,   g_h16);
    cudaGetSymbolAddress((void**)&wh16,  g_wh16);
    cudaGetSymbolAddress((void**)&wmh16, g_wmh16);

    cudaFuncSetAttribute(tc_gemm_kernel<0>, cudaFuncAttributeMaxDynamicSharedMemorySize, SMEM_T);
    cudaFuncSetAttribute(tc_gemm_kernel<1>, cudaFuncAttributeMaxDynamicSharedMemorySize, SMEM_T);

    // fork: side stream for the GEMM-z-only prep chain
    cudaStream_t s2;
    cudaEvent_t evF, evJ;
    cudaStreamCreateWithFlags(&s2, cudaStreamNonBlocking);
    cudaEventCreateWithFlags(&evF, cudaEventDisableTiming);
    cudaEventCreateWithFlags(&evJ, cudaEventDisableTiming);
    cudaEventRecord(evF, 0);
    cudaStreamWaitEvent(s2, evF, 0);

    // ---- chain B (s2): prep needed only by GEMM-z ----
    colnorm_kernel<<<(H4 + 31) / 32, 256, 0, s2>>>(wx, gx, sx, DIN, H4);
    colnorm_kernel<<<(H4 + 31) / 32, 256, 0, s2>>>(wh, gh, sh, H_DIM, H4);
    input_gemm_gates<<<(int)(((long long)B_DIM * H4 + 255) / 256), 256, 0, s2>>>(inputs, wx, sx, bvec, zx16);
    {
        dim3 blk(32, 32);
        dim3 gz((H4 + 31) / 32, KP / 32);
        transp_h16_kernel<1><<<gz, blk, 0, s2>>>(wh, sh, wh16, H_DIM, H4);
    }
    cudaEventRecord(evJ, s2);

    // ---- chain A (stream 0): GEMM-m path ----
    colnorm_kernel<<<(H_DIM + 31) / 32, 256>>>(wmx, gmx, smx, DIN, H_DIM);
    colnorm_kernel<<<(H_DIM + 31) / 32, 256>>>(wmh, gmh, smh, H_DIM, H_DIM);
    input_gemm_plain<<<(int)(((long long)B_DIM * H_DIM + 255) / 256), 256>>>(inputs, wmx, smx, xm16);
    pad_h16_kernel<<<(int)(((long long)B_DIM * KP + 255) / 256), 256>>>(h_prev, h16, H_DIM, (long long)B_DIM * KP);
    {
        dim3 blk(32, 32);
        dim3 gm((H_DIM + 31) / 32, KP / 32);
        transp_h16_kernel<0><<<gm, blk>>>(wmh, smh, wmh16, H_DIM, H_DIM);
    }
    {
        dim3 grid(NP_M / 128, B_DIM / 128);
        tc_gemm_kernel<0><<<grid, 256, SMEM_T>>>(h16, wmh16,
                                                 xm16, nullptr, nullptr, nullptr, nullptr, m16);
    }

    // join, then GEMM-z
    cudaStreamWaitEvent(0, evJ, 0);
    {
        dim3 grid(NP_Z / 128, B_DIM / 128);
        tc_gemm_kernel<1><<<grid, 256, SMEM_T>>>(m16, wh16,
                                                 nullptr, zx16, c_prev, out_h, out_c, nullptr);
    }
    (void)in_sizes; (void)n_in; (void)out_size;
}